// round 11
// baseline (speedup 1.0000x reference)
#include <cuda_runtime.h>
#include <cuda_fp16.h>
#include <cstdint>

#define Bsz     32768
#define Dd      1024
#define Cc      40
#define CT      80            // 40 fwd + 40 rev output columns
#define RB      128           // rows (M) per CTA -> 256 CTAs
#define THREADS 256           // 8 warps: 4 M-warps x 2 N-warps
#define KC      32            // k per chunk
#define NCH     (Dd / KC)     // 32
#define NAST    5             // A ring depth (cp.async, wait_group 3 -> 4-deep lookahead)

#define PADK    36                        // A fp32 floats/row (144B) - LDS.64 conflict-free
#define A_STAGE_B (RB * PADK * 4)         // 18432
#define AROWB   80                        // B fp16 row bytes (64 data + 16 pad) - LDSM conflict-free
#define B_STAGE_B (CT * AROWB)            // 6400
#define OFF_A0  1024
#define OFF_B0  (OFF_A0 + NAST * A_STAGE_B)        // 93184
#define SMEM_BYTES (OFF_B0 + 2 * B_STAGE_B)        // 105984 -> 2 CTAs/SM

// epilogue overlay (aliases rings after mainloop)
#define BROW    81
#define EPI_BASE_F 256
#define EPI_WT_F   (EPI_BASE_F + RB * BROW)
#define EPI_BB_F   (EPI_WT_F + 2 * Cc * Cc)

__device__ __half Wh[CT * Dd];   // fp16 copy of GEMM part of [W;W_rev]

extern __shared__ float smf[];

__device__ __forceinline__ uint32_t pk(float lo, float hi) {
    uint32_t r;
    asm("cvt.rn.f16x2.f32 %0, %1, %2;" : "=r"(r) : "f"(hi), "f"(lo));
    return r;
}

__device__ __forceinline__ void mma_16x8x16(float* d, const uint32_t* a,
                                            const uint32_t* bf) {
    asm volatile(
        "mma.sync.aligned.m16n8k16.row.col.f32.f16.f16.f32 "
        "{%0,%1,%2,%3}, {%4,%5,%6,%7}, {%8,%9}, {%0,%1,%2,%3};"
        : "+f"(d[0]), "+f"(d[1]), "+f"(d[2]), "+f"(d[3])
        : "r"(a[0]), "r"(a[1]), "r"(a[2]), "r"(a[3]), "r"(bf[0]), "r"(bf[1]));
}

__device__ __forceinline__ void ldsm4(uint32_t* r, uint32_t a) {
    asm volatile("ldmatrix.sync.aligned.m8n8.x4.shared.b16 {%0,%1,%2,%3}, [%4];"
                 : "=r"(r[0]), "=r"(r[1]), "=r"(r[2]), "=r"(r[3]) : "r"(a));
}
__device__ __forceinline__ void ldsm2(uint32_t* r, uint32_t a) {
    asm volatile("ldmatrix.sync.aligned.m8n8.x2.shared.b16 {%0,%1}, [%2];"
                 : "=r"(r[0]), "=r"(r[1]) : "r"(a));
}

__global__ void convert_w(const float* __restrict__ W,
                          const float* __restrict__ Wr) {
    const int idx = blockIdx.x * 256 + threadIdx.x;
    if (idx < CT * Dd) {
        const int r = idx >> 10, k = idx & 1023;
        const float* Wp = (r < Cc) ? W  + (size_t)r        * (Dd + Cc)
                                   : Wr + (size_t)(r - Cc) * (Dd + Cc);
        Wh[idx] = __float2half_rn(Wp[k]);
    }
}

__global__ void __launch_bounds__(THREADS, 2)
bichain_d5(const float* __restrict__ src,
           const float* __restrict__ W,  const float* __restrict__ b,
           const float* __restrict__ Wr, const float* __restrict__ br,
           float* __restrict__ out) {
    const int tid  = threadIdx.x;
    const int warp = tid >> 5;
    const int lane = tid & 31;
    const int row0 = blockIdx.x * RB;

    uint32_t smb;
    asm("{ .reg .u64 t; cvta.to.shared.u64 t, %1; cvt.u32.u64 %0, t; }"
        : "=r"(smb) : "l"(smf));

    // ---- producer A (cp.async, 5-deep ring, the DRAM stream) ----
    const int arow = tid >> 3, aseg = tid & 7;
    const float* gA[4];
    uint32_t dA[4];
    #pragma unroll
    for (int i = 0; i < 4; ++i) {
        gA[i] = src + (size_t)(row0 + arow + 32 * i) * Dd + aseg * 4;
        dA[i] = (uint32_t)((arow + 32 * i) * (PADK * 4) + aseg * 16);
    }
    auto issueA = [&](int ch) {
        if (ch < NCH) {
            const uint32_t aS = smb + OFF_A0 + (uint32_t)(ch % NAST) * A_STAGE_B;
            const int k0 = ch * KC;
            #pragma unroll
            for (int i = 0; i < 4; ++i)
                asm volatile("cp.async.cg.shared.global [%0], [%1], 16;"
                             :: "r"(aS + dA[i]), "l"(gA[i] + k0));
        }
        asm volatile("cp.async.commit_group;");   // uniform accounting
    };

    // ---- producer B (register-staged LDG + STS; L2-resident, 2-deep) ----
    const int br_ = tid >> 2, bseg = tid & 3;
    const __half* gB = Wh + (size_t)br_ * Dd + bseg * 8;
    const uint32_t dB = (uint32_t)(br_ * AROWB + bseg * 16);
    uint4 bcur[2], bnxt[2];
    auto ldgB = [&](int ch, uint4* rr) {
        if (ch < NCH) {
            const uint4* p = (const uint4*)(gB + ch * KC);
            rr[0] = p[0];
            if (tid < 64) rr[1] = *(const uint4*)((const __half*)p + 64 * Dd);
        }
    };
    auto stsB = [&](const uint4* rr, uint32_t sbase) {
        asm volatile("st.shared.v4.b32 [%0], {%1,%2,%3,%4};"
                     :: "r"(sbase + dB), "r"(rr[0].x), "r"(rr[0].y),
                        "r"(rr[0].z), "r"(rr[0].w));
        if (tid < 64)
            asm volatile("st.shared.v4.b32 [%0], {%1,%2,%3,%4};"
                         :: "r"(sbase + dB + 64 * AROWB), "r"(rr[1].x),
                            "r"(rr[1].y), "r"(rr[1].z), "r"(rr[1].w));
    };

    // ---- consumer offsets ----
    const int mw = warp >> 1, nw = warp & 1;
    const int qr = lane >> 2, qc = lane & 3;
    const int g8 = lane >> 3, i8 = lane & 7;

    int rA2[2][2];                       // A float2 indices (stage-relative)
    #pragma unroll
    for (int mt = 0; mt < 2; ++mt) {
        const int r = mw * 32 + mt * 16 + qr;
        rA2[mt][0] = r * (PADK / 2) + qc;
        rA2[mt][1] = (r + 8) * (PADK / 2) + qc;
    }
    uint32_t boff[2][2], boffc[2];       // B ldmatrix byte offsets (stage-relative)
    #pragma unroll
    for (int p = 0; p < 2; ++p)
        #pragma unroll
        for (int kk = 0; kk < 2; ++kk)
            boff[p][kk] = (uint32_t)((nw * 40 + p * 16 + (g8 >> 1) * 8 + i8) * AROWB
                                     + (g8 & 1) * 16 + kk * 32);
    {
        const int l2g = (lane & 15) >> 3;
        #pragma unroll
        for (int kk = 0; kk < 2; ++kk)
            boffc[kk] = (uint32_t)((nw * 40 + 32 + i8) * AROWB + l2g * 16 + kk * 32);
    }

    float acc[2][5][4];
    #pragma unroll
    for (int mt = 0; mt < 2; ++mt)
        #pragma unroll
        for (int t = 0; t < 5; ++t)
            #pragma unroll
            for (int e = 0; e < 4; ++e) acc[mt][t][e] = 0.f;

    // ---- prologue: A(0..3) in flight; B(0) in smem stage0; B(1) in regs ----
    issueA(0); issueA(1); issueA(2); issueA(3);
    ldgB(0, bcur);
    stsB(bcur, smb + OFF_B0);
    ldgB(1, bcur);
    __syncthreads();

    for (int ch = 0; ch < NCH; ++ch) {
        // pending A groups: {ch..ch+3} -> release when A(ch) lands
        asm volatile("cp.async.wait_group 3;");
        __syncthreads();                 // A(ch) visible; stage (ch-1)%5 & B (ch+1)&1 free
        issueA(ch + 4);
        if (ch + 1 < NCH) stsB(bcur, smb + OFF_B0 + ((ch + 1) & 1) * B_STAGE_B);
        ldgB(ch + 2, bnxt);

        const float2* Ap2 =
            (const float2*)((const char*)smf + OFF_A0 + (ch % NAST) * A_STAGE_B);
        const uint32_t sbB = smb + OFF_B0 + (uint32_t)(ch & 1) * B_STAGE_B;

        #pragma unroll
        for (int kk = 0; kk < 2; ++kk) {
            const int kb2 = kk * 8;
            uint32_t afr[2][4], q0[4], q1[4], q2[2];
            #pragma unroll
            for (int mt = 0; mt < 2; ++mt) {
                float2 p0 = Ap2[rA2[mt][0] + kb2];
                float2 p1 = Ap2[rA2[mt][1] + kb2];
                float2 p2 = Ap2[rA2[mt][0] + kb2 + 4];
                float2 p3 = Ap2[rA2[mt][1] + kb2 + 4];
                afr[mt][0] = pk(p0.x, p0.y);
                afr[mt][1] = pk(p1.x, p1.y);
                afr[mt][2] = pk(p2.x, p2.y);
                afr[mt][3] = pk(p3.x, p3.y);
            }
            ldsm4(q0, sbB + boff[0][kk]);
            ldsm4(q1, sbB + boff[1][kk]);
            ldsm2(q2, sbB + boffc[kk]);
            mma_16x8x16(acc[0][0], afr[0], q0);
            mma_16x8x16(acc[0][1], afr[0], q0 + 2);
            mma_16x8x16(acc[0][2], afr[0], q1);
            mma_16x8x16(acc[0][3], afr[0], q1 + 2);
            mma_16x8x16(acc[0][4], afr[0], q2);
            mma_16x8x16(acc[1][0], afr[1], q0);
            mma_16x8x16(acc[1][1], afr[1], q0 + 2);
            mma_16x8x16(acc[1][2], afr[1], q1);
            mma_16x8x16(acc[1][3], afr[1], q1 + 2);
            mma_16x8x16(acc[1][4], afr[1], q2);
        }

        bcur[0] = bnxt[0];
        bcur[1] = bnxt[1];
    }
    __syncthreads();   // all stages consumed before overlay writes

    // ---- accumulators -> smem bases[128][81] ----
    float* bases = smf + EPI_BASE_F;
    #pragma unroll
    for (int mt = 0; mt < 2; ++mt) {
        const int r = mw * 32 + mt * 16 + qr;
        #pragma unroll
        for (int t = 0; t < 5; ++t) {
            const int c = nw * 40 + t * 8 + qc * 2;
            bases[(r    ) * BROW + c    ] = acc[mt][t][0];
            bases[(r    ) * BROW + c + 1] = acc[mt][t][1];
            bases[(r + 8) * BROW + c    ] = acc[mt][t][2];
            bases[(r + 8) * BROW + c + 1] = acc[mt][t][3];
        }
    }

    // chain tail weights W[:,1024:1064] + biases (fp32 originals)
    float* wt = smf + EPI_WT_F;
    float* bb = smf + EPI_BB_F;
    for (int idx = tid; idx < 2 * Cc * Cc; idx += THREADS) {
        const int chn = idx / (Cc * Cc);
        const int rem = idx - chn * Cc * Cc;
        const int i = rem / Cc, j = rem % Cc;
        const float* Wp = chn ? Wr : W;
        wt[idx] = Wp[(size_t)i * (Dd + Cc) + Dd + j];
    }
    if (tid < 2 * Cc) bb[tid] = (tid < Cc) ? b[tid] : br[tid - Cc];
    __syncthreads();

    // ---- sequential chains: 256 threads = 128 rows x 2 chains ----
    {
        const int row = tid >> 1, chn = tid & 1;
        float* my        = bases + row * BROW + chn * Cc;
        const float* wtc = wt + chn * Cc * Cc;
        const float* bbc = bb + chn * Cc;
        float s[Cc];
        #pragma unroll
        for (int i = 0; i < Cc; ++i) {
            float x = my[i] + bbc[i];
            #pragma unroll
            for (int j = 0; j < i; ++j)
                x = fmaf(s[j], wtc[i * Cc + j], x);
            s[i] = 1.0f / (1.0f + __expf(-x));
            my[i] = s[i];
        }
    }
    __syncthreads();

    // ---- combine fwd + reversed rev, coalesced store ----
    #pragma unroll
    for (int it = 0; it < (RB * Cc) / THREADS; ++it) {   // 20
        const int idx = tid + it * THREADS;
        const int r = idx / Cc, c = idx - r * Cc;
        const float vf = bases[r * BROW + c];
        const float vr = bases[r * BROW + Cc + (Cc - 1 - c)];
        out[(size_t)(row0 + r) * Cc + c] = 0.5f * (vf + vr);
    }
}

extern "C" void kernel_launch(void* const* d_in, const int* in_sizes, int n_in,
                              void* d_out, int out_size) {
    const float* src = (const float*)d_in[0];
    // d_in[1] = attn_mask (unused)
    const float* W   = (const float*)d_in[2];
    const float* b   = (const float*)d_in[3];
    const float* Wr  = (const float*)d_in[4];
    const float* br  = (const float*)d_in[5];
    float* out = (float*)d_out;

    convert_w<<<(CT * Dd + 255) / 256, 256>>>(W, Wr);
    cudaFuncSetAttribute(bichain_d5,
                         cudaFuncAttributeMaxDynamicSharedMemorySize, SMEM_BYTES);
    bichain_d5<<<Bsz / RB, THREADS, SMEM_BYTES>>>(src, W, b, Wr, br, out);
}

// round 12
// speedup vs baseline: 1.2626x; 1.2626x over previous
#include <cuda_runtime.h>
#include <cuda_fp16.h>
#include <cstdint>

#define Bsz     32768
#define Dd      1024
#define Cc      40
#define CT      80            // 40 fwd + 40 rev output columns
#define RB      128           // rows (M) per CTA -> 256 CTAs
#define THREADS 256           // 8 warps: 4 M-warps x 2 N-warps
#define KC      32            // k per chunk
#define NCH     (Dd / KC)     // 32
#define NST     4             // ring depth

#define PADK    40                        // A fp32 floats/row (160B): (4qr+qc)%16 all-distinct
#define A_STAGE_B (RB * PADK * 4)         // 20480
#define AROWB   80                        // B fp16 row bytes - LDSM conflict-free
#define B_STAGE_B (CT * AROWB)            // 6400
#define OFF_A0  1024
#define OFF_B0  (OFF_A0 + NST * A_STAGE_B)     // 82944
#define SMEM_BYTES (OFF_B0 + NST * B_STAGE_B)  // 108544 -> 2 CTAs/SM

// epilogue overlay (aliases rings after mainloop)
#define BROW    81
#define EPI_BASE_F 256
#define EPI_WT_F   (EPI_BASE_F + RB * BROW)
#define EPI_BB_F   (EPI_WT_F + 2 * Cc * Cc)

__device__ __half Wh[CT * Dd];   // fp16 copy of GEMM part of [W;W_rev]

extern __shared__ float smf[];

__device__ __forceinline__ uint32_t pk(float lo, float hi) {
    uint32_t r;
    asm("cvt.rn.f16x2.f32 %0, %1, %2;" : "=r"(r) : "f"(hi), "f"(lo));
    return r;
}

__device__ __forceinline__ void mma_16x8x16(float* d, const uint32_t* a,
                                            const uint32_t* bf) {
    asm volatile(
        "mma.sync.aligned.m16n8k16.row.col.f32.f16.f16.f32 "
        "{%0,%1,%2,%3}, {%4,%5,%6,%7}, {%8,%9}, {%0,%1,%2,%3};"
        : "+f"(d[0]), "+f"(d[1]), "+f"(d[2]), "+f"(d[3])
        : "r"(a[0]), "r"(a[1]), "r"(a[2]), "r"(a[3]), "r"(bf[0]), "r"(bf[1]));
}

__device__ __forceinline__ void ldsm4(uint32_t* r, uint32_t a) {
    asm volatile("ldmatrix.sync.aligned.m8n8.x4.shared.b16 {%0,%1,%2,%3}, [%4];"
                 : "=r"(r[0]), "=r"(r[1]), "=r"(r[2]), "=r"(r[3]) : "r"(a));
}
__device__ __forceinline__ void ldsm2(uint32_t* r, uint32_t a) {
    asm volatile("ldmatrix.sync.aligned.m8n8.x2.shared.b16 {%0,%1}, [%2];"
                 : "=r"(r[0]), "=r"(r[1]) : "r"(a));
}

__global__ void convert_w(const float* __restrict__ W,
                          const float* __restrict__ Wr) {
    const int idx = blockIdx.x * 256 + threadIdx.x;
    if (idx < CT * Dd) {
        const int r = idx >> 10, k = idx & 1023;
        const float* Wp = (r < Cc) ? W  + (size_t)r        * (Dd + Cc)
                                   : Wr + (size_t)(r - Cc) * (Dd + Cc);
        Wh[idx] = __float2half_rn(Wp[k]);
    }
}

__global__ void __launch_bounds__(THREADS, 2)
bichain_r12(const float* __restrict__ src,
            const float* __restrict__ W,  const float* __restrict__ b,
            const float* __restrict__ Wr, const float* __restrict__ br,
            float* __restrict__ out) {
    const int tid  = threadIdx.x;
    const int warp = tid >> 5;
    const int lane = tid & 31;
    const int row0 = blockIdx.x * RB;

    uint32_t smb;
    asm("{ .reg .u64 t; cvta.to.shared.u64 t, %1; cvt.u32.u64 %0, t; }"
        : "=r"(smb) : "l"(smf));

    // ---- producer mapping (identical to R10) ----
    const int arow = tid >> 3, aseg = tid & 7;
    const float* gA[4];
    uint32_t dA[4];
    #pragma unroll
    for (int i = 0; i < 4; ++i) {
        gA[i] = src + (size_t)(row0 + arow + 32 * i) * Dd + aseg * 4;
        dA[i] = (uint32_t)((arow + 32 * i) * (PADK * 4) + aseg * 16);
    }
    const int brow = tid >> 2, bseg = tid & 3;
    const __half* gB0 = Wh + (size_t)brow * Dd + bseg * 8;
    const __half* gB1 = Wh + (size_t)(brow + 64) * Dd + bseg * 8;
    const uint32_t dB0 = (uint32_t)(brow * AROWB + bseg * 16);
    const uint32_t dB1 = (uint32_t)((brow + 64) * AROWB + bseg * 16);

    auto issue = [&](int ch) {
        if (ch < NCH) {
            const uint32_t aS = smb + OFF_A0 + (uint32_t)(ch & 3) * A_STAGE_B;
            const uint32_t bS = smb + OFF_B0 + (uint32_t)(ch & 3) * B_STAGE_B;
            const int k0 = ch * KC;
            #pragma unroll
            for (int i = 0; i < 4; ++i)
                asm volatile("cp.async.cg.shared.global [%0], [%1], 16;"
                             :: "r"(aS + dA[i]), "l"(gA[i] + k0));
            asm volatile("cp.async.ca.shared.global [%0], [%1], 16;"
                         :: "r"(bS + dB0), "l"(gB0 + k0));
            if (tid < 64)
                asm volatile("cp.async.ca.shared.global [%0], [%1], 16;"
                             :: "r"(bS + dB1), "l"(gB1 + k0));
        }
        asm volatile("cp.async.commit_group;");   // uniform accounting
    };

    // ---- consumer offsets ----
    const int mw = warp >> 1, nw = warp & 1;
    const int qr = lane >> 2, qc = lane & 3;
    const int g8 = lane >> 3, i8 = lane & 7;

    int rA2[2][2];
    #pragma unroll
    for (int mt = 0; mt < 2; ++mt) {
        const int r = mw * 32 + mt * 16 + qr;
        rA2[mt][0] = r * (PADK / 2) + qc;
        rA2[mt][1] = (r + 8) * (PADK / 2) + qc;
    }
    uint32_t boff[2][2], boffc[2];
    #pragma unroll
    for (int p = 0; p < 2; ++p)
        #pragma unroll
        for (int kk = 0; kk < 2; ++kk)
            boff[p][kk] = (uint32_t)((nw * 40 + p * 16 + (g8 >> 1) * 8 + i8) * AROWB
                                     + (g8 & 1) * 16 + kk * 32);
    {
        const int l2g = (lane & 15) >> 3;
        #pragma unroll
        for (int kk = 0; kk < 2; ++kk)
            boffc[kk] = (uint32_t)((nw * 40 + 32 + i8) * AROWB + l2g * 16 + kk * 32);
    }

    float acc[2][5][4];
    #pragma unroll
    for (int mt = 0; mt < 2; ++mt)
        #pragma unroll
        for (int t = 0; t < 5; ++t)
            #pragma unroll
            for (int e = 0; e < 4; ++e) acc[mt][t][e] = 0.f;

    // ---- prologue: 3 chunks in flight ----
    issue(0); issue(1); issue(2);

    for (int ch = 0; ch < NCH; ++ch) {
        asm volatile("cp.async.wait_group 2;");
        __syncthreads();
        issue(ch + 3);

        const float2* Ap2 =
            (const float2*)((const char*)smf + OFF_A0 + (ch & 3) * A_STAGE_B);
        const uint32_t sbB = smb + OFF_B0 + (uint32_t)(ch & 3) * B_STAGE_B;

        #pragma unroll
        for (int kk = 0; kk < 2; ++kk) {
            const int kb2 = kk * 8;
            uint32_t afr[2][4], q0[4], q1[4], q2[2];
            #pragma unroll
            for (int mt = 0; mt < 2; ++mt) {
                float2 p0 = Ap2[rA2[mt][0] + kb2];
                float2 p1 = Ap2[rA2[mt][1] + kb2];
                float2 p2 = Ap2[rA2[mt][0] + kb2 + 4];
                float2 p3 = Ap2[rA2[mt][1] + kb2 + 4];
                afr[mt][0] = pk(p0.x, p0.y);
                afr[mt][1] = pk(p1.x, p1.y);
                afr[mt][2] = pk(p2.x, p2.y);
                afr[mt][3] = pk(p3.x, p3.y);
            }
            ldsm4(q0, sbB + boff[0][kk]);
            ldsm4(q1, sbB + boff[1][kk]);
            ldsm2(q2, sbB + boffc[kk]);
            mma_16x8x16(acc[0][0], afr[0], q0);
            mma_16x8x16(acc[0][1], afr[0], q0 + 2);
            mma_16x8x16(acc[0][2], afr[0], q1);
            mma_16x8x16(acc[0][3], afr[0], q1 + 2);
            mma_16x8x16(acc[0][4], afr[0], q2);
            mma_16x8x16(acc[1][0], afr[1], q0);
            mma_16x8x16(acc[1][1], afr[1], q0 + 2);
            mma_16x8x16(acc[1][2], afr[1], q1);
            mma_16x8x16(acc[1][3], afr[1], q1 + 2);
            mma_16x8x16(acc[1][4], afr[1], q2);
        }
    }
    __syncthreads();   // last stage consumed everywhere before overlay writes

    // ---- epilogue: prefetch chain weights into regs FIRST (overlaps writeback) ----
    float wreg[13];
    int   widx[13];
    #pragma unroll
    for (int k = 0; k < 13; ++k) {
        const int idx = tid + k * THREADS;
        widx[k] = idx;
        if (idx < 2 * Cc * Cc) {
            const int chn = idx / (Cc * Cc);
            const int rem = idx - chn * Cc * Cc;
            const int i = rem / Cc, j = rem - i * Cc;
            const float* Wp = chn ? Wr : W;
            wreg[k] = Wp[(size_t)i * (Dd + Cc) + Dd + j];
        }
    }
    float breg = 0.f;
    if (tid < 2 * Cc) breg = (tid < Cc) ? b[tid] : br[tid - Cc];

    // ---- accumulators -> smem bases[128][81] (overlaps the LDGs above) ----
    float* bases = smf + EPI_BASE_F;
    #pragma unroll
    for (int mt = 0; mt < 2; ++mt) {
        const int r = mw * 32 + mt * 16 + qr;
        #pragma unroll
        for (int t = 0; t < 5; ++t) {
            const int c = nw * 40 + t * 8 + qc * 2;
            bases[(r    ) * BROW + c    ] = acc[mt][t][0];
            bases[(r    ) * BROW + c + 1] = acc[mt][t][1];
            bases[(r + 8) * BROW + c    ] = acc[mt][t][2];
            bases[(r + 8) * BROW + c + 1] = acc[mt][t][3];
        }
    }

    float* wt = smf + EPI_WT_F;
    float* bb = smf + EPI_BB_F;
    #pragma unroll
    for (int k = 0; k < 13; ++k)
        if (widx[k] < 2 * Cc * Cc) wt[widx[k]] = wreg[k];
    if (tid < 2 * Cc) bb[tid] = breg;
    __syncthreads();

    // ---- sequential chains: 256 threads = 128 rows x 2 chains ----
    // inner j-loop split into two alternating partials (halves serial FMA depth)
    {
        const int row = tid >> 1, chn = tid & 1;
        float* my        = bases + row * BROW + chn * Cc;
        const float* wtc = wt + chn * Cc * Cc;
        const float* bbc = bb + chn * Cc;
        float s[Cc];
        #pragma unroll
        for (int i = 0; i < Cc; ++i) {
            float x0 = my[i] + bbc[i];
            float x1 = 0.f;
            #pragma unroll
            for (int j = 0; j + 1 < i; j += 2) {
                x0 = fmaf(s[j],     wtc[i * Cc + j],     x0);
                x1 = fmaf(s[j + 1], wtc[i * Cc + j + 1], x1);
            }
            if (i & 1) x0 = fmaf(s[i - 1], wtc[i * Cc + i - 1], x0);
            const float x = x0 + x1;
            s[i] = 1.0f / (1.0f + __expf(-x));
            my[i] = s[i];
        }
    }
    __syncthreads();

    // ---- combine fwd + reversed rev, coalesced store ----
    #pragma unroll
    for (int it = 0; it < (RB * Cc) / THREADS; ++it) {   // 20
        const int idx = tid + it * THREADS;
        const int r = idx / Cc, c = idx - r * Cc;
        const float vf = bases[r * BROW + c];
        const float vr = bases[r * BROW + Cc + (Cc - 1 - c)];
        out[(size_t)(row0 + r) * Cc + c] = 0.5f * (vf + vr);
    }
}

extern "C" void kernel_launch(void* const* d_in, const int* in_sizes, int n_in,
                              void* d_out, int out_size) {
    const float* src = (const float*)d_in[0];
    // d_in[1] = attn_mask (unused)
    const float* W   = (const float*)d_in[2];
    const float* b   = (const float*)d_in[3];
    const float* Wr  = (const float*)d_in[4];
    const float* br  = (const float*)d_in[5];
    float* out = (float*)d_out;

    convert_w<<<(CT * Dd + 255) / 256, 256>>>(W, Wr);
    cudaFuncSetAttribute(bichain_r12,
                         cudaFuncAttributeMaxDynamicSharedMemorySize, SMEM_BYTES);
    bichain_r12<<<Bsz / RB, THREADS, SMEM_BYTES>>>(src, W, b, Wr, br, out);
}